// round 5
// baseline (speedup 1.0000x reference)
#include <cuda_runtime.h>
#include <cstdint>

#define SEQ 2048
#define DIM 128
#define BHN 32
#define NROWS (BHN * SEQ)   // 65536 rows each for q and k

// Scratch: reciprocal L2 norms (no device allocation allowed -> __device__ globals)
__device__ float g_rq[NROWS];
__device__ float g_rk[NROWS];

// ---------------------------------------------------------------------------
// Kernel 1: per-row 1/max(||x||, 1e-12). One warp per row.
// ---------------------------------------------------------------------------
__global__ void norm_kernel(const float* __restrict__ q, const float* __restrict__ k) {
    int gwarp = (blockIdx.x * blockDim.x + threadIdx.x) >> 5;
    int lane = threadIdx.x & 31;
    bool is_q = gwarp < NROWS;
    int row = is_q ? gwarp : gwarp - NROWS;
    const float* src = is_q ? q : k;
    float4 v = reinterpret_cast<const float4*>(src + (size_t)row * DIM)[lane];
    float ss = v.x * v.x + v.y * v.y + v.z * v.z + v.w * v.w;
#pragma unroll
    for (int o = 16; o > 0; o >>= 1) ss += __shfl_xor_sync(0xffffffffu, ss, o);
    if (lane == 0) {
        float r = 1.0f / fmaxf(sqrtf(ss), 1e-12f);
        if (is_q) g_rq[row] = r; else g_rk[row] = r;
    }
}

// ---------------------------------------------------------------------------
// Helpers
// ---------------------------------------------------------------------------
__device__ __forceinline__ uint32_t smem_to_u32(const void* p) {
    uint32_t a;
    asm("{ .reg .u64 t; cvta.to.shared.u64 t, %1; cvt.u32.u64 %0, t; }" : "=r"(a) : "l"(p));
    return a;
}

#define CP_ASYNC16(dst, src) \
    asm volatile("cp.async.ca.shared.global [%0], [%1], 16;" :: "r"(dst), "l"(src))
#define CP_COMMIT() asm volatile("cp.async.commit_group;" ::: "memory")
#define CP_WAIT(n)  asm volatile("cp.async.wait_group %0;" :: "n"(n) : "memory")

__device__ __forceinline__ void ldsm_x4(unsigned r[4], uint32_t addr) {
    asm volatile("ldmatrix.sync.aligned.m8n8.x4.shared.b16 {%0,%1,%2,%3}, [%4];"
                 : "=r"(r[0]), "=r"(r[1]), "=r"(r[2]), "=r"(r[3]) : "r"(addr));
}

__device__ __forceinline__ void mma_tf32(float c[4], const unsigned a[4],
                                         unsigned b0, unsigned b1) {
    asm volatile(
        "mma.sync.aligned.m16n8k8.row.col.f32.tf32.tf32.f32 "
        "{%0,%1,%2,%3}, {%4,%5,%6,%7}, {%8,%9}, {%0,%1,%2,%3};\n"
        : "+f"(c[0]), "+f"(c[1]), "+f"(c[2]), "+f"(c[3])
        : "r"(a[0]), "r"(a[1]), "r"(a[2]), "r"(a[3]), "r"(b0), "r"(b1));
}

// ---------------------------------------------------------------------------
// Kernel 2: persistent-over-bn GEMM + exp epilogue.
// CTA = (bh, bm, bn-octet). A tile (128 q-rows, K=128) resident for all 8
// bn tiles; B tiles (128 k-rows) double-buffered via cp.async so tile t+1's
// load overlaps tile t's MMAs. Warp grid 2x4, warp tile 64x32.
// smem (floats, padded rows LDA=132):
//   As[128][132]  at 0        (67584 B)
//   B0[128][132]  at 67584
//   B1[128][132]  at 135168   total 202752 B
// ---------------------------------------------------------------------------
#define LDA 132
#define SM_B0 67584
#define SM_B1 135168
#define SMEM_TOTAL 202752

__global__ __launch_bounds__(256, 1) void tc_gemm_exp_kernel(
    const float* __restrict__ q, const float* __restrict__ k,
    const float* __restrict__ logt, float* __restrict__ out)
{
    extern __shared__ char smem[];
    uint32_t sbase = smem_to_u32(smem);

    int bh = blockIdx.z;
    int bm = blockIdx.y;          // 16 tiles of 128 q-rows
    int bn0 = blockIdx.x * 8;     // 2 octets of 8 bn-tiles
    int tid = threadIdx.x;
    int warp = tid >> 5, lane = tid & 31;
    int wm = warp >> 2, wn = warp & 3;   // 2 x 4 warp grid
    int wmo = wm * 64, wno = wn * 32;    // warp tile 64 x 32

    const float* qb = q + ((size_t)bh * SEQ + (size_t)bm * 128) * DIM;

    // ---- issue A + first B loads ----
#pragma unroll
    for (int i = 0; i < 16; i++) {
        int id = tid + i * 256, r = id >> 5, c4 = id & 31;
        CP_ASYNC16(sbase + (uint32_t)((r * LDA + c4 * 4) * 4),
                   qb + (size_t)r * DIM + c4 * 4);
    }
    {
        const float* kb = k + ((size_t)bh * SEQ + (size_t)bn0 * 128) * DIM;
#pragma unroll
        for (int i = 0; i < 16; i++) {
            int id = tid + i * 256, r = id >> 5, c4 = id & 31;
            CP_ASYNC16(sbase + SM_B0 + (uint32_t)((r * LDA + c4 * 4) * 4),
                       kb + (size_t)r * DIM + c4 * 4);
        }
    }
    CP_COMMIT();

    // ---- fragment addresses ----
    int g = lane >> 3, lr = lane & 7;
    uint32_t aA[4];
    uint32_t bOff[2];
#pragma unroll
    for (int mi = 0; mi < 4; mi++)
        aA[mi] = sbase +
            (uint32_t)(((wmo + mi * 16 + (g & 1) * 8 + lr) * LDA + (g >> 1) * 4) * 4);
#pragma unroll
    for (int p = 0; p < 2; p++)
        bOff[p] = (uint32_t)(((wno + p * 16 + (g >> 1) * 8 + lr) * LDA + (g & 1) * 4) * 4);

    // ---- scalars (hoisted) ----
    const float LOG2E = 1.442695040888963f;
    float lt = *logt;
    float temp = fminf(fmaxf(__expf(lt), 0.05f), 100.0f);
    float scl = LOG2E / temp;        // fold 1/temp and log2(e)
    float cl = 100.0f * LOG2E;       // clamp bound in log2 domain

    int gid = lane >> 2, tig = lane & 3;
    float rqv[4][2];
    {
        const float* rqp = g_rq + (size_t)bh * SEQ + (size_t)bm * 128;
#pragma unroll
        for (int mi = 0; mi < 4; mi++) {
            int r0 = wmo + mi * 16 + gid;
            rqv[mi][0] = rqp[r0];
            rqv[mi][1] = rqp[r0 + 8];
        }
    }

    // ---- persistent bn loop ----
    for (int t = 0; t < 8; t++) {
        int bn = bn0 + t;
        uint32_t smB = sbase + ((t & 1) ? SM_B1 : SM_B0);

        CP_WAIT(0);
        __syncthreads();

        // prefetch next B into the other buffer (consumed two iters ago)
        if (t < 7) {
            const float* kbn = k + ((size_t)bh * SEQ + (size_t)(bn + 1) * 128) * DIM;
            uint32_t dstB = sbase + ((t & 1) ? SM_B0 : SM_B1);
#pragma unroll
            for (int i = 0; i < 16; i++) {
                int id = tid + i * 256, r = id >> 5, c4 = id & 31;
                CP_ASYNC16(dstB + (uint32_t)((r * LDA + c4 * 4) * 4),
                           kbn + (size_t)r * DIM + c4 * 4);
            }
            CP_COMMIT();
        }

        // ---- MMA mainloop with in-warp fragment pipelining ----
        float acc[4][4][4];
#pragma unroll
        for (int mi = 0; mi < 4; mi++)
#pragma unroll
            for (int ni = 0; ni < 4; ni++)
#pragma unroll
                for (int r = 0; r < 4; r++) acc[mi][ni][r] = 0.0f;

        unsigned af[2][4][4], bf[2][2][4];
#pragma unroll
        for (int mi = 0; mi < 4; mi++) ldsm_x4(af[0][mi], aA[mi]);
#pragma unroll
        for (int p = 0; p < 2; p++) ldsm_x4(bf[0][p], smB + bOff[p]);

#pragma unroll
        for (int s = 0; s < 16; s++) {
            int cur = s & 1, nxt = cur ^ 1;
            if (s < 15) {
                uint32_t kbyt = (uint32_t)((s + 1) * 32);
#pragma unroll
                for (int mi = 0; mi < 4; mi++) ldsm_x4(af[nxt][mi], aA[mi] + kbyt);
#pragma unroll
                for (int p = 0; p < 2; p++) ldsm_x4(bf[nxt][p], smB + bOff[p] + kbyt);
            }
#pragma unroll
            for (int mi = 0; mi < 4; mi++)
#pragma unroll
                for (int p = 0; p < 2; p++) {
                    mma_tf32(acc[mi][2 * p],     af[cur][mi], bf[cur][p][0], bf[cur][p][1]);
                    mma_tf32(acc[mi][2 * p + 1], af[cur][mi], bf[cur][p][2], bf[cur][p][3]);
                }
        }

        // ---- epilogue ----
        const float* rkp = g_rk + (size_t)bh * SEQ + (size_t)bn * 128;
        float rkv[4][2];
#pragma unroll
        for (int ni = 0; ni < 4; ni++) {
            int c0 = wno + ni * 8 + tig * 2;
            float2 v = *reinterpret_cast<const float2*>(rkp + c0);
            rkv[ni][0] = v.x * scl;
            rkv[ni][1] = v.y * scl;
        }

#pragma unroll
        for (int mi = 0; mi < 4; mi++) {
            int r0 = wmo + mi * 16 + gid;
            float* o0p = out + ((size_t)bh * SEQ + (size_t)(bm * 128 + r0)) * SEQ
                             + (size_t)bn * 128;
            float* o1p = o0p + (size_t)8 * SEQ;
            float rq0 = rqv[mi][0], rq1 = rqv[mi][1];
#pragma unroll
            for (int ni = 0; ni < 4; ni++) {
                int c0 = wno + ni * 8 + tig * 2;
                float x00 = fminf(fmaxf(acc[mi][ni][0] * rq0 * rkv[ni][0], -cl), cl);
                float x01 = fminf(fmaxf(acc[mi][ni][1] * rq0 * rkv[ni][1], -cl), cl);
                float x10 = fminf(fmaxf(acc[mi][ni][2] * rq1 * rkv[ni][0], -cl), cl);
                float x11 = fminf(fmaxf(acc[mi][ni][3] * rq1 * rkv[ni][1], -cl), cl);
                float2 o0, o1;
                o0.x = exp2f(x00) + 1e-6f;
                o0.y = exp2f(x01) + 1e-6f;
                o1.x = exp2f(x10) + 1e-6f;
                o1.y = exp2f(x11) + 1e-6f;
                *reinterpret_cast<float2*>(o0p + c0) = o0;
                *reinterpret_cast<float2*>(o1p + c0) = o1;
            }
        }
        // no extra sync: next iteration's CP_WAIT(0)+__syncthreads() guards
        // both the buffer swap and the prefetch issued above.
    }
}

// ---------------------------------------------------------------------------
// Launcher (graph-capturable: kernel launches only)
// ---------------------------------------------------------------------------
extern "C" void kernel_launch(void* const* d_in, const int* in_sizes, int n_in,
                              void* d_out, int out_size) {
    const float* q  = (const float*)d_in[0];
    const float* k  = (const float*)d_in[1];
    const float* lt = (const float*)d_in[2];
    float* out = (float*)d_out;

    norm_kernel<<<(2 * NROWS) / 8, 256>>>(q, k);

    cudaFuncSetAttribute(tc_gemm_exp_kernel,
                         cudaFuncAttributeMaxDynamicSharedMemorySize, SMEM_TOTAL);
    dim3 grid(2, 16, 32);  // (bn-octet, bm, bh)
    tc_gemm_exp_kernel<<<grid, 256, SMEM_TOTAL>>>(q, k, lt, out);
}

// round 6
// speedup vs baseline: 1.2597x; 1.2597x over previous
#include <cuda_runtime.h>
#include <cstdint>

#define SEQ 2048
#define DIM 128
#define BHN 32
#define NROWS (BHN * SEQ)   // 65536 rows each for q and k

// Scratch: reciprocal L2 norms (no device allocation allowed -> __device__ globals)
__device__ float g_rq[NROWS];
__device__ float g_rk[NROWS];

// ---------------------------------------------------------------------------
// Kernel 1: per-row 1/max(||x||, 1e-12). One warp per row.
// ---------------------------------------------------------------------------
__global__ void norm_kernel(const float* __restrict__ q, const float* __restrict__ k) {
    int gwarp = (blockIdx.x * blockDim.x + threadIdx.x) >> 5;
    int lane = threadIdx.x & 31;
    bool is_q = gwarp < NROWS;
    int row = is_q ? gwarp : gwarp - NROWS;
    const float* src = is_q ? q : k;
    float4 v = reinterpret_cast<const float4*>(src + (size_t)row * DIM)[lane];
    float ss = v.x * v.x + v.y * v.y + v.z * v.z + v.w * v.w;
#pragma unroll
    for (int o = 16; o > 0; o >>= 1) ss += __shfl_xor_sync(0xffffffffu, ss, o);
    if (lane == 0) {
        float r = 1.0f / fmaxf(sqrtf(ss), 1e-12f);
        if (is_q) g_rq[row] = r; else g_rk[row] = r;
    }
}

// ---------------------------------------------------------------------------
// Helpers
// ---------------------------------------------------------------------------
__device__ __forceinline__ uint32_t smem_to_u32(const void* p) {
    uint32_t a;
    asm("{ .reg .u64 t; cvta.to.shared.u64 t, %1; cvt.u32.u64 %0, t; }" : "=r"(a) : "l"(p));
    return a;
}

#define CP_ASYNC16(dst, src) \
    asm volatile("cp.async.ca.shared.global [%0], [%1], 16;" :: "r"(dst), "l"(src))
#define CP_COMMIT() asm volatile("cp.async.commit_group;" ::: "memory")
#define CP_WAIT(n)  asm volatile("cp.async.wait_group %0;" :: "n"(n) : "memory")

__device__ __forceinline__ void ldsm_x4(unsigned r[4], uint32_t addr) {
    asm volatile("ldmatrix.sync.aligned.m8n8.x4.shared.b16 {%0,%1,%2,%3}, [%4];"
                 : "=r"(r[0]), "=r"(r[1]), "=r"(r[2]), "=r"(r[3]) : "r"(addr));
}

__device__ __forceinline__ void mma_tf32(float c[4], const unsigned a[4],
                                         unsigned b0, unsigned b1) {
    asm volatile(
        "mma.sync.aligned.m16n8k8.row.col.f32.tf32.tf32.f32 "
        "{%0,%1,%2,%3}, {%4,%5,%6,%7}, {%8,%9}, {%0,%1,%2,%3};\n"
        : "+f"(c[0]), "+f"(c[1]), "+f"(c[2]), "+f"(c[3])
        : "r"(a[0]), "r"(a[1]), "r"(a[2]), "r"(a[3]), "r"(b0), "r"(b1));
}

__device__ __forceinline__ float ex2f(float x) {
    float y;
    asm("ex2.approx.f32 %0, %1;" : "=f"(y) : "f"(x));
    return y;
}

// ---------------------------------------------------------------------------
// Kernel 2: K-chunked pipelined GEMM + exp epilogue. 2 CTAs/SM.
// Tile: M=128 x N=128, K chunks of 32, 2 smem stages.
// Warp grid 2x4, warp tile 64x32. 256 threads, <=128 regs (launch_bounds).
// smem per stage: A[128][36] + B[128][36] fp32 (row stride 36 floats keeps
// ldmatrix 8-row pointer sets on distinct 16B banks). Stage = 36864 B.
// Total = 2 stages * 36864 = 73728 B -> 2 CTAs/SM.
// ---------------------------------------------------------------------------
#define LDC 36
#define CH_BYTES (128 * LDC * 4)          // 18432 per matrix chunk
#define STAGE_BYTES (2 * CH_BYTES)        // 36864
#define SMEM_TOTAL (2 * STAGE_BYTES)      // 73728

__global__ __launch_bounds__(256, 2) void tc_gemm_exp_kernel(
    const float* __restrict__ q, const float* __restrict__ k,
    const float* __restrict__ logt, float* __restrict__ out)
{
    extern __shared__ char smem[];
    uint32_t sbase = smem_to_u32(smem);

    int bh = blockIdx.z;
    int bm = blockIdx.y;
    int bn = blockIdx.x;
    int tid = threadIdx.x;
    int warp = tid >> 5, lane = tid & 31;
    int wm = warp >> 2, wn = warp & 3;   // 2 x 4 warp grid
    int wmo = wm * 64, wno = wn * 32;    // warp tile 64 x 32

    const float* qb = q + ((size_t)bh * SEQ + (size_t)bm * 128) * DIM;
    const float* kb = k + ((size_t)bh * SEQ + (size_t)bn * 128) * DIM;

    // cp.async indices: 1024 float4 per chunk matrix -> 4 per thread
    int ldr = tid >> 3;           // row 0..31 base (x4 rows per iter)
    int ldc4 = tid & 7;           // float4 col 0..7

    // issue chunk c into stage s
    auto issue_chunk = [&](int c, int s) {
        uint32_t stA = sbase + (uint32_t)(s * STAGE_BYTES);
        uint32_t stB = stA + CH_BYTES;
        const float* qsrc = qb + c * 32 + ldc4 * 4;
        const float* ksrc = kb + c * 32 + ldc4 * 4;
#pragma unroll
        for (int i = 0; i < 4; i++) {
            int r = ldr + i * 32;
            uint32_t o = (uint32_t)((r * LDC + ldc4 * 4) * 4);
            CP_ASYNC16(stA + o, qsrc + (size_t)r * DIM);
            CP_ASYNC16(stB + o, ksrc + (size_t)r * DIM);
        }
        CP_COMMIT();
    };

    issue_chunk(0, 0);
    issue_chunk(1, 1);

    // fragment offsets within a stage
    int g = lane >> 3, lr = lane & 7;
    uint32_t aOff[4], bOff[2];
#pragma unroll
    for (int mi = 0; mi < 4; mi++)
        aOff[mi] = (uint32_t)(((wmo + mi * 16 + (g & 1) * 8 + lr) * LDC + (g >> 1) * 4) * 4);
#pragma unroll
    for (int p = 0; p < 2; p++)
        bOff[p] = (uint32_t)(((wno + p * 16 + (g >> 1) * 8 + lr) * LDC + (g & 1) * 4) * 4) + CH_BYTES;

    float acc[4][4][4];
#pragma unroll
    for (int mi = 0; mi < 4; mi++)
#pragma unroll
        for (int ni = 0; ni < 4; ni++)
#pragma unroll
            for (int r = 0; r < 4; r++) acc[mi][ni][r] = 0.0f;

    // ---- chunk loop: 4 chunks of K=32 ----
#pragma unroll
    for (int c = 0; c < 4; c++) {
        if (c < 3) CP_WAIT(1); else CP_WAIT(0);
        __syncthreads();
        uint32_t st = sbase + (uint32_t)((c & 1) * STAGE_BYTES);

#pragma unroll
        for (int s = 0; s < 4; s++) {
            uint32_t kbyt = (uint32_t)(s * 32);
            unsigned af[4][4], bf[2][4];
#pragma unroll
            for (int mi = 0; mi < 4; mi++) ldsm_x4(af[mi], st + aOff[mi] + kbyt);
#pragma unroll
            for (int p = 0; p < 2; p++) ldsm_x4(bf[p], st + bOff[p] + kbyt);
#pragma unroll
            for (int mi = 0; mi < 4; mi++)
#pragma unroll
                for (int p = 0; p < 2; p++) {
                    mma_tf32(acc[mi][2 * p],     af[mi], bf[p][0], bf[p][1]);
                    mma_tf32(acc[mi][2 * p + 1], af[mi], bf[p][2], bf[p][3]);
                }
        }

        if (c < 2) {
            __syncthreads();          // all warps done reading this stage
            issue_chunk(c + 2, c & 1);
        }
    }

    // ---- epilogue (no clamp needed: |score| <= 20 < 100 always) ----
    const float LOG2E = 1.442695040888963f;
    float lt = *logt;
    float temp = fminf(fmaxf(__expf(lt), 0.05f), 100.0f);
    float scl = LOG2E / temp;

    int gid = lane >> 2, tig = lane & 3;
    const float* rqp = g_rq + (size_t)bh * SEQ + (size_t)bm * 128;
    const float* rkp = g_rk + (size_t)bh * SEQ + (size_t)bn * 128;

    float rkv[4][2];
#pragma unroll
    for (int ni = 0; ni < 4; ni++) {
        int c0 = wno + ni * 8 + tig * 2;
        float2 v = *reinterpret_cast<const float2*>(rkp + c0);
        rkv[ni][0] = v.x * scl;
        rkv[ni][1] = v.y * scl;
    }

#pragma unroll
    for (int mi = 0; mi < 4; mi++) {
        int r0 = wmo + mi * 16 + gid;
        float rq0 = rqp[r0];
        float rq1 = rqp[r0 + 8];
        float* o0p = out + ((size_t)bh * SEQ + (size_t)(bm * 128 + r0)) * SEQ
                         + (size_t)bn * 128;
        float* o1p = o0p + (size_t)8 * SEQ;
#pragma unroll
        for (int ni = 0; ni < 4; ni++) {
            int c0 = wno + ni * 8 + tig * 2;
            float2 o0, o1;
            o0.x = ex2f(acc[mi][ni][0] * rq0 * rkv[ni][0]) + 1e-6f;
            o0.y = ex2f(acc[mi][ni][1] * rq0 * rkv[ni][1]) + 1e-6f;
            o1.x = ex2f(acc[mi][ni][2] * rq1 * rkv[ni][0]) + 1e-6f;
            o1.y = ex2f(acc[mi][ni][3] * rq1 * rkv[ni][1]) + 1e-6f;
            *reinterpret_cast<float2*>(o0p + c0) = o0;
            *reinterpret_cast<float2*>(o1p + c0) = o1;
        }
    }
}

// ---------------------------------------------------------------------------
// Launcher (graph-capturable: kernel launches only)
// ---------------------------------------------------------------------------
extern "C" void kernel_launch(void* const* d_in, const int* in_sizes, int n_in,
                              void* d_out, int out_size) {
    const float* q  = (const float*)d_in[0];
    const float* k  = (const float*)d_in[1];
    const float* lt = (const float*)d_in[2];
    float* out = (float*)d_out;

    norm_kernel<<<(2 * NROWS) / 8, 256>>>(q, k);

    cudaFuncSetAttribute(tc_gemm_exp_kernel,
                         cudaFuncAttributeMaxDynamicSharedMemorySize, SMEM_TOTAL);
    dim3 grid(16, 16, 32);  // (bn, bm, bh)
    tc_gemm_exp_kernel<<<grid, 256, SMEM_TOTAL>>>(q, k, lt, out);
}